// round 17
// baseline (speedup 1.0000x reference)
#include <cuda_runtime.h>
#include <cuda_bf16.h>
#include <math.h>
#include <stdint.h>

#define HD    512
#define GATES 2048
#define NB    1024
#define SEQ   256
#define CH    128
#define NCLS  40
#define NBLK  128          // 8 m-tiles (128 rows) x 16 j-tiles, 1 CTA/SM
#define NTHR  256
#define NGRP  16           // blocks per barrier group (same mt, all jt)

// stage (u32): A hi/lo (128 rows) + B1 hi/lo + B0 hi/lo, RSTRIDE-padded
#define RSTRIDE 36
#define A_TILE_U32 (128 * RSTRIDE)     // 4608
#define B_TILE_U32 (128 * RSTRIDE)     // 4608
#define STAGE_U32 (6 * A_TILE_U32)     // 27648
#define SMEM_SZ (2 * STAGE_U32 * 4)    // 221184 bytes (1 CTA/SM)
// u32 offsets inside a stage
#define OFF_AHI 0
#define OFF_ALO A_TILE_U32
#define OFF_B1  (2 * A_TILE_U32)
#define OFF_B0  (4 * A_TILE_U32)

// precomputed hi/lo bf16 weights, packed per (layer, jt, superchunk) tile [128][64]
#define W0_NCH 10
#define W1_NCH 16
#define W0_TILES (16 * W0_NCH)
#define W1_TILES (16 * W1_NCH)
#define WTILE 8192
#define WN ((W0_TILES + W1_TILES) * WTILE)

// ---------------- persistent device scratch ---------------------------------
__device__ __nv_bfloat16 g_whi[WN];
__device__ __nv_bfloat16 g_wlo[WN];
__device__ float g_h0[2][NB * HD];
__device__ float g_c0[NB * HD];
__device__ float g_h1[2][NB * HD];
__device__ float g_c1[NB * HD];
__device__ float g_cls_sum;
__device__ float g_bbox_sum;
__device__ int   g_correct;
__device__ unsigned g_bar_count;
__device__ unsigned g_bar_phase;            // monotonic across replays
__device__ unsigned g_grp_count[16 * 32];
__device__ unsigned g_grp_phase[16 * 32];

// ---------------- helpers ----------------------------------------------------
__device__ __forceinline__ uint32_t smem_u32(const void* p) {
    uint32_t a;
    asm("{ .reg .u64 t; cvta.to.shared.u64 t, %1; cvt.u32.u64 %0, t; }"
        : "=r"(a) : "l"(p));
    return a;
}
__device__ __forceinline__ uint32_t packbf(float x, float y) {
    uint32_t r;
    asm("cvt.rn.bf16x2.f32 %0, %1, %2;" : "=r"(r) : "f"(y), "f"(x));
    return r;
}
__device__ __forceinline__ float fsig(float x) {
    float e, r;
    asm("ex2.approx.ftz.f32 %0, %1;" : "=f"(e) : "f"(-1.4426950408889634f * x));
    asm("rcp.approx.ftz.f32 %0, %1;" : "=f"(r) : "f"(1.f + e));
    return r;
}
__device__ __forceinline__ float ftanh(float x) {
    float e, r;
    asm("ex2.approx.ftz.f32 %0, %1;" : "=f"(e) : "f"(-2.885390081777927f * x));
    asm("rcp.approx.ftz.f32 %0, %1;" : "=f"(r) : "f"(1.f + e));
    return 2.f * r - 1.f;
}
__device__ __forceinline__ void mma_bf16(float* d, const uint32_t* a,
                                         uint32_t b0, uint32_t b1) {
    asm("mma.sync.aligned.m16n8k16.row.col.f32.bf16.bf16.f32 "
        "{%0,%1,%2,%3}, {%4,%5,%6,%7}, {%8,%9}, {%0,%1,%2,%3};"
        : "+f"(d[0]), "+f"(d[1]), "+f"(d[2]), "+f"(d[3])
        : "r"(a[0]), "r"(a[1]), "r"(a[2]), "r"(a[3]), "r"(b0), "r"(b1));
}
__device__ __forceinline__ void ldsm_x4(uint32_t* r, uint32_t addr) {
    asm volatile("ldmatrix.sync.aligned.m8n8.x4.shared.b16 {%0,%1,%2,%3}, [%4];"
        : "=r"(r[0]), "=r"(r[1]), "=r"(r[2]), "=r"(r[3]) : "r"(addr));
}
#define CP16(dst, src) asm volatile("cp.async.cg.shared.global [%0], [%1], 16;" :: "r"(dst), "l"(src) : "memory")
#define CP_COMMIT()    asm volatile("cp.async.commit_group;" ::: "memory")
#define CP_WAIT0()     asm volatile("cp.async.wait_group 0;" ::: "memory")

// ---------------- barriers ----------------------------------------------------
__device__ __forceinline__ void grid_bar(unsigned& my_phase) {
    __syncthreads();
    if (threadIdx.x == 0) {
        __threadfence();
        unsigned old = atomicAdd(&g_bar_count, 1u);
        if (old == NBLK - 1) {
            g_bar_count = 0;
            __threadfence();
            atomicExch(&g_bar_phase, my_phase + 1u);
        } else {
            while (atomicAdd(&g_bar_phase, 0u) <= my_phase) __nanosleep(64);
        }
        __threadfence();
    }
    my_phase++;
    __syncthreads();
}
__device__ __forceinline__ void group_bar(int grp, unsigned& my_phase) {
    __syncthreads();
    if (threadIdx.x == 0) {
        __threadfence();
        unsigned old = atomicAdd(&g_grp_count[grp * 32], 1u);
        if (old == NGRP - 1) {
            g_grp_count[grp * 32] = 0;
            __threadfence();
            atomicExch(&g_grp_phase[grp * 32], my_phase + 1u);
        } else {
            int spins = 0;
            while (atomicAdd(&g_grp_phase[grp * 32], 0u) <= my_phase) {
                if (++spins > 4) __nanosleep(40);
            }
        }
        __threadfence();
    }
    my_phase++;
    __syncthreads();
}

// ---------------- cell epilogue (mf=4 variant) -------------------------------
__device__ __forceinline__ void cell_epilogue(
    float (*d)[4][4], int lane, int m0w, int n0w, int tr, int tc,
    int row0, int j0, const float* __restrict__ bias,
    float* __restrict__ cbuf, float* __restrict__ hout)
{
    #pragma unroll
    for (int mf = 0; mf < 4; ++mf) {
        #pragma unroll
        for (int nf = 0; nf < 4; ++nf) {
            float v0 = d[mf][nf][0], v1 = d[mf][nf][1];
            float v2 = d[mf][nf][2], v3 = d[mf][nf][3];
            float r0 = __shfl_xor_sync(0xffffffffu, v0, 1);
            float r1 = __shfl_xor_sync(0xffffffffu, v1, 1);
            float r2 = __shfl_xor_sync(0xffffffffu, v2, 1);
            float r3 = __shfl_xor_sync(0xffffffffu, v3, 1);
            if ((lane & 1) == 0) {
                int col = n0w + nf * 8 + tc * 2;
                int jj  = j0 + (col >> 2);
                int m   = row0 + m0w + mf * 16 + tr;
                float b0v = bias[jj], b1v = bias[HD + jj];
                float b2v = bias[2 * HD + jj], b3v = bias[3 * HD + jj];
                {
                    float si = fsig(v0 + b0v);
                    float sf = fsig(v1 + b1v);
                    float so = fsig(r1 + b3v);
                    size_t ix = (size_t)m * HD + jj;
                    float cv = sf * cbuf[ix] + si * ftanh(r0 + b2v);
                    cbuf[ix] = cv;
                    hout[ix] = so * ftanh(cv);
                }
                {
                    float si = fsig(v2 + b0v);
                    float sf = fsig(v3 + b1v);
                    float so = fsig(r3 + b3v);
                    size_t ix = (size_t)(m + 8) * HD + jj;
                    float cv = sf * cbuf[ix] + si * ftanh(r2 + b2v);
                    cbuf[ix] = cv;
                    hout[ix] = so * ftanh(cv);
                }
            }
        }
    }
}

// ---------------- fused dual-layer span --------------------------------------
// Shared-A: h0cur chunks (8) feed BOTH L1(t) (weights wb1) and L0(t+1) (wb0).
// Then h1prev chunks (8, L1 only), then x chunks (2, L0 only).
__device__ __forceinline__ void lstm_span(
    int use_d1, int use_d0,
    const float* __restrict__ h0cur, const float* __restrict__ h1prev,
    const float* __restrict__ xnext,
    int wb1, int wb0,
    const float* __restrict__ bias1, float* __restrict__ c1,
    float* __restrict__ h1out,
    const float* __restrict__ bias0, float* __restrict__ c0,
    float* __restrict__ h0out,
    uint32_t* smU, uint32_t su)
{
    const int tid  = threadIdx.x;
    const int lane = tid & 31;
    const int w    = tid >> 5;
    const int m0w  = (w >> 2) * 64;        // 2 m-warp-groups x 64 rows
    const int n0w  = (w & 3) * 32;
    const int tr   = lane >> 2;
    const int tc   = lane & 3;
    const int row0 = (blockIdx.x >> 4) * 128;
    const int j0   = (blockIdx.x & 15) * 32;
    const int nt   = 8 + (use_d1 ? 8 : 0) + (use_d0 ? 2 : 0);
    const int lrow16 = lane & 15;
    const int lkoff  = (lane >> 4) << 2;

    uint32_t aoffs[4], boffs[2];
    #pragma unroll
    for (int mf = 0; mf < 4; ++mf)
        aoffs[mf] = (uint32_t)(((m0w + mf * 16 + lrow16) * RSTRIDE + lkoff) * 4);
    #pragma unroll
    for (int np = 0; np < 2; ++np)
        boffs[np] = (uint32_t)(((n0w + np * 16 + lrow16) * RSTRIDE + lkoff) * 4);

    float d1[4][4][4], d0[4][4][4];
    #pragma unroll
    for (int mf = 0; mf < 4; ++mf)
        #pragma unroll
        for (int nf = 0; nf < 4; ++nf)
            #pragma unroll
            for (int q = 0; q < 4; ++q) { d1[mf][nf][q] = 0.f; d0[mf][nf][q] = 0.f; }

    float4 a4[8];

    // chunk metadata
    #define CINFO(u_, Ap_, astr_, k0_, wt1_, wt0_)  do {                       \
        if ((u_) < 8) {                                                        \
            Ap_ = h0cur; astr_ = HD; k0_ = (u_) * 64;                          \
            wt1_ = use_d1 ? wb1 + (u_) : -1;                                   \
            wt0_ = use_d0 ? wb0 + 2 + (u_) : -1;                               \
        } else if (use_d1 && (u_) < 16) {                                      \
            Ap_ = h1prev; astr_ = HD; k0_ = ((u_) - 8) * 64;                   \
            wt1_ = wb1 + (u_); wt0_ = -1;                                      \
        } else {                                                               \
            int v_ = (u_) - (use_d1 ? 16 : 8);                                 \
            Ap_ = xnext; astr_ = SEQ * CH; k0_ = v_ * 64;                      \
            wt1_ = -1; wt0_ = wb0 + v_;                                        \
        } } while (0)

    #define LDG_A(Ap_, astr_, k0_)  do {                                       \
        _Pragma("unroll")                                                      \
        for (int l = 0; l < 8; ++l) {                                          \
            int idx = tid + l * 256; int r = idx >> 4, fc = idx & 15;          \
            a4[l] = *reinterpret_cast<const float4*>(                          \
                &Ap_[(size_t)(row0 + r) * (astr_) + (k0_) + fc * 4]);          \
        } } while (0)

    #define ST_A(s_)  do {                                                     \
        uint32_t* aHi = smU + (s_) * STAGE_U32 + OFF_AHI;                      \
        uint32_t* aLo = smU + (s_) * STAGE_U32 + OFF_ALO;                      \
        _Pragma("unroll")                                                      \
        for (int l = 0; l < 8; ++l) {                                          \
            int idx = tid + l * 256; int r = idx >> 4, fc = idx & 15;          \
            int so = r * RSTRIDE + fc * 2;                                     \
            float4 v = a4[l];                                                  \
            float hx = __bfloat162float(__float2bfloat16(v.x));                \
            float hy = __bfloat162float(__float2bfloat16(v.y));                \
            float hz = __bfloat162float(__float2bfloat16(v.z));                \
            float hw = __bfloat162float(__float2bfloat16(v.w));                \
            uint2 hv, lv;                                                      \
            hv.x = packbf(v.x, v.y);        hv.y = packbf(v.z, v.w);           \
            lv.x = packbf(v.x - hx, v.y - hy); lv.y = packbf(v.z - hz, v.w - hw); \
            *reinterpret_cast<uint2*>(&aHi[so]) = hv;                          \
            *reinterpret_cast<uint2*>(&aLo[so]) = lv;                          \
        } } while (0)

    #define CP_B(wt_, regoff_, s_)  do {                                       \
        const __nv_bfloat16* srcHi = g_whi + (size_t)(wt_) * WTILE;            \
        const __nv_bfloat16* srcLo = g_wlo + (size_t)(wt_) * WTILE;            \
        uint32_t bHiA = su + ((s_) * STAGE_U32 + (regoff_)) * 4u;              \
        uint32_t bLoA = bHiA + B_TILE_U32 * 4u;                                \
        _Pragma("unroll")                                                      \
        for (int l = 0; l < 4; ++l) {                                          \
            int idx = tid + l * 256; int r = idx >> 3, p = idx & 7;            \
            uint32_t doff = (uint32_t)(r * (RSTRIDE * 4) + p * 16);            \
            int soff = r * 64 + p * 8;                                         \
            CP16(bHiA + doff, srcHi + soff);                                   \
            CP16(bLoA + doff, srcLo + soff);                                   \
        } } while (0)

    // 3-term passes for one layer into acc
    #define MMA_LAYER(acc_, bbase_)  do {                                      \
        uint32_t bh[2][4], bl[2][4];                                           \
        _Pragma("unroll")                                                      \
        for (int np = 0; np < 2; ++np) {                                       \
            uint32_t ba = (bbase_) + boffs[np] + kbB;                          \
            ldsm_x4(bh[np], ba);                                               \
            ldsm_x4(bl[np], ba + B_TILE_U32 * 4u);                             \
        }                                                                      \
        _Pragma("unroll")                                                      \
        for (int nf = 0; nf < 4; ++nf) {                                       \
            const int np = nf >> 1, sel = nf & 1;                              \
            _Pragma("unroll")                                                  \
            for (int mf = 0; mf < 4; ++mf)                                     \
                mma_bf16(acc_[mf][nf], ah[mf], bh[np][sel], bh[np][sel + 2]);  \
        }                                                                      \
        _Pragma("unroll")                                                      \
        for (int nf = 0; nf < 4; ++nf) {                                       \
            const int np = nf >> 1, sel = nf & 1;                              \
            _Pragma("unroll")                                                  \
            for (int mf = 0; mf < 4; ++mf)                                     \
                mma_bf16(acc_[mf][nf], ah[mf], bl[np][sel], bl[np][sel + 2]);  \
        }                                                                      \
        _Pragma("unroll")                                                      \
        for (int nf = 0; nf < 4; ++nf) {                                       \
            const int np = nf >> 1, sel = nf & 1;                              \
            _Pragma("unroll")                                                  \
            for (int mf = 0; mf < 4; ++mf)                                     \
                mma_bf16(acc_[mf][nf], al[mf], bh[np][sel], bh[np][sel + 2]);  \
        } } while (0)

    // guard smem-stage reuse against the previous span's tail reads
    __syncthreads();

    // prologue: chunk 0 into stage 0
    {
        const float* Ap; int astr, k0, wt1, wt0;
        CINFO(0, Ap, astr, k0, wt1, wt0);
        if (wt1 >= 0) CP_B(wt1, OFF_B1, 0);
        if (wt0 >= 0) CP_B(wt0, OFF_B0, 0);
        CP_COMMIT();
        LDG_A(Ap, astr, k0);
        ST_A(0);
    }

    for (int u = 0; u < nt; ++u) {
        const int s = u & 1;
        const bool pf = (u + 1 < nt);
        if (pf) {
            const float* Ap; int astr, k0, wt1n, wt0n;
            CINFO(u + 1, Ap, astr, k0, wt1n, wt0n);
            LDG_A(Ap, astr, k0);
        }
        CP_WAIT0();
        __syncthreads();
        if (pf) {
            const float* Ap; int astr, k0, wt1n, wt0n;
            CINFO(u + 1, Ap, astr, k0, wt1n, wt0n);
            if (wt1n >= 0) CP_B(wt1n, OFF_B1, 1 - s);
            if (wt0n >= 0) CP_B(wt0n, OFF_B0, 1 - s);
            CP_COMMIT();
        }

        // current chunk activity
        const float* ApC; int astrC, k0C, wt1c, wt0c;
        CINFO(u, ApC, astrC, k0C, wt1c, wt0c);

        const uint32_t stage = su + (uint32_t)(s * STAGE_U32) * 4u;
        const uint32_t b1base = stage + OFF_B1 * 4u;
        const uint32_t b0base = stage + OFF_B0 * 4u;

        #pragma unroll
        for (int kg = 0; kg < 4; ++kg) {
            const uint32_t kbB = (uint32_t)(kg * 8 * 4);
            uint32_t ah[4][4], al[4][4];
            #pragma unroll
            for (int mf = 0; mf < 4; ++mf) {
                uint32_t aa = stage + aoffs[mf] + kbB;
                ldsm_x4(ah[mf], aa);
                ldsm_x4(al[mf], aa + A_TILE_U32 * 4u);
            }
            if (wt1c >= 0) MMA_LAYER(d1, b1base);
            if (wt0c >= 0) MMA_LAYER(d0, b0base);
        }

        if (pf) ST_A(1 - s);

        // L1 epilogue mid-pipeline once its 16 chunks are done
        if (use_d1 && u == 15)
            cell_epilogue(d1, lane, m0w, n0w, tr, tc, row0, j0, bias1, c1, h1out);
    }

    if (use_d0)
        cell_epilogue(d0, lane, m0w, n0w, tr, tc, row0, j0, bias0, c0, h0out);

    #undef CINFO
    #undef LDG_A
    #undef ST_A
    #undef CP_B
    #undef MMA_LAYER
}

// ---------------- whole network, one persistent kernel -----------------------
__global__ __launch_bounds__(NTHR, 1)
void rlstm_persistent(const float* __restrict__ data,
                      const int*   __restrict__ labels,
                      const float* __restrict__ props,
                      const float* __restrict__ Wih0, const float* __restrict__ Whh0,
                      const float* __restrict__ b0,
                      const float* __restrict__ Wih1, const float* __restrict__ Whh1,
                      const float* __restrict__ b1,
                      const float* __restrict__ Wcls, const float* __restrict__ bcls,
                      const float* __restrict__ Wbbox, const float* __restrict__ bbbox,
                      float* __restrict__ out)
{
    extern __shared__ uint32_t smU[];
    uint32_t su = smem_u32(smU);
    const int tid = threadIdx.x;
    const int grp = blockIdx.x >> 4;
    unsigned ph  = atomicAdd(&g_bar_phase, 0u);
    unsigned gph = atomicAdd(&g_grp_phase[grp * 32], 0u);

    for (int i = blockIdx.x * NTHR + tid; i < NB * HD; i += NBLK * NTHR) {
        g_h0[0][i] = 0.f; g_h1[0][i] = 0.f;
        g_c0[i] = 0.f;    g_c1[i] = 0.f;
    }
    if (blockIdx.x == 0 && tid == 0) {
        g_cls_sum = 0.f; g_bbox_sum = 0.f; g_correct = 0;
    }
    // precompute hi/lo bf16 weights, packed [128][64] per (jt, superchunk)
    for (int i = blockIdx.x * NTHR + tid; i < WN; i += NBLK * NTHR) {
        int tile = i >> 13, e = i & 8191;
        int r = e >> 6, k = e & 63;
        int jt, kk;
        const float* B; int bstr, k0;
        if (tile < W0_TILES) {
            jt = tile / W0_NCH; kk = tile % W0_NCH;
            if (kk < 2) { B = Wih0; bstr = CH; k0 = kk * 64; }
            else        { B = Whh0; bstr = HD; k0 = (kk - 2) * 64; }
        } else {
            int t2 = tile - W0_TILES;
            jt = t2 / W1_NCH; kk = t2 % W1_NCH;
            if (kk < 8) { B = Wih1; bstr = HD; k0 = kk * 64; }
            else        { B = Whh1; bstr = HD; k0 = (kk - 8) * 64; }
        }
        int grow = (r & 3) * HD + jt * 32 + (r >> 2);
        float v = B[(size_t)grow * bstr + k0 + k];
        __nv_bfloat16 hb = __float2bfloat16(v);
        g_whi[i] = hb;
        g_wlo[i] = __float2bfloat16(v - __bfloat162float(hb));
    }
    grid_bar(ph);

    const int jt = blockIdx.x & 15;
    const int wbase0 = jt * W0_NCH;
    const int wbase1 = W0_TILES + jt * W1_NCH;

    // span -1: L0(0) only
    lstm_span(0, 1, g_h0[0], nullptr, data, wbase1, wbase0,
              b1, g_c1, nullptr, b0, g_c0, g_h0[1], smU, su);
    group_bar(grp, gph);
    // span t: L1(t) + L0(t+1) fused over shared h0cur, one barrier per step
    for (int t = 0; t < SEQ; ++t) {
        int p = t & 1;
        const bool last = (t + 1 == SEQ);
        lstm_span(1, last ? 0 : 1,
                  g_h0[1 - p], g_h1[p], data + (size_t)(t + 1) * CH,
                  wbase1, wbase0,
                  b1, g_c1, g_h1[1 - p],
                  b0, g_c0, g_h0[p], smU, su);
        group_bar(grp, gph);
    }
    grid_bar(ph);

    // heads + loss on final hidden state g_h1[0]; 8 rows per block
    {
        float* hrow = (float*)smU;
        float* cls  = hrow + HD;
        for (int r = 0; r < 8; ++r) {
            int n = blockIdx.x * 8 + r;
            for (int j = tid; j < HD; j += NTHR)
                hrow[j] = g_h1[0][(size_t)n * HD + j];
            __syncthreads();
            if (tid < NCLS) {
                float s = bcls[tid];
                const float* wp = Wcls + (size_t)tid * HD;
                #pragma unroll 8
                for (int j = 0; j < HD; ++j) s += hrow[j] * wp[j];
                cls[tid] = s;
            } else if (tid < NCLS + 2) {
                int pp = tid - NCLS;
                float s = bbbox[pp];
                const float* wp = Wbbox + (size_t)pp * HD;
                #pragma unroll 8
                for (int j = 0; j < HD; ++j) s += hrow[j] * wp[j];
                float tg = props[n * 2 + pp] * (1.0f / (float)SEQ);
                float dd = fabsf(s - tg);
                float sl = (dd < 1.f) ? 0.5f * dd * dd : dd - 0.5f;
                atomicAdd(&g_bbox_sum, sl);
            }
            __syncthreads();
            if (tid == 0) {
                float mx = cls[0]; int am = 0;
                for (int k = 1; k < NCLS; ++k)
                    if (cls[k] > mx) { mx = cls[k]; am = k; }
                float se = 0.f;
                for (int k = 0; k < NCLS; ++k) se += expf(cls[k] - mx);
                float lse = mx + logf(se);
                int lbl = labels[n * 2];
                atomicAdd(&g_cls_sum, -(cls[lbl] - lse));
                if (am == lbl) atomicAdd(&g_correct, 1);
            }
            __syncthreads();
        }
    }
    grid_bar(ph);

    if (blockIdx.x == 0 && tid == 0) {
        out[0] = (g_cls_sum / (float)NB) / (1.0f + (float)g_correct);
        out[1] = (g_bbox_sum / (float)(NB * 2)) * 10.0f;
    }
}

// ---------------- launch: ONE graph node -------------------------------------
extern "C" void kernel_launch(void* const* d_in, const int* in_sizes, int n_in,
                              void* d_out, int out_size) {
    const float* data   = (const float*)d_in[0];
    const int*   labels = (const int*)  d_in[1];
    const float* props  = (const float*)d_in[2];
    const float* Wih0   = (const float*)d_in[3];
    const float* Whh0   = (const float*)d_in[4];
    const float* b0     = (const float*)d_in[5];
    const float* Wih1   = (const float*)d_in[6];
    const float* Whh1   = (const float*)d_in[7];
    const float* b1     = (const float*)d_in[8];
    const float* Wcls   = (const float*)d_in[9];
    const float* bcls   = (const float*)d_in[10];
    const float* Wbbox  = (const float*)d_in[11];
    const float* bbbox  = (const float*)d_in[12];
    float* out = (float*)d_out;

    cudaFuncSetAttribute(rlstm_persistent,
                         cudaFuncAttributeMaxDynamicSharedMemorySize, SMEM_SZ);
    rlstm_persistent<<<NBLK, NTHR, SMEM_SZ>>>(data, labels, props,
                                              Wih0, Whh0, b0, Wih1, Whh1, b1,
                                              Wcls, bcls, Wbbox, bbbox, out);
}